// round 5
// baseline (speedup 1.0000x reference)
#include <cuda_runtime.h>

#define NF 27
#define FD 128
#define ROW_ELEMS (NF * FD)          // 3456
#define NPAIRS (NF * (NF - 1) / 2)   // 351
#define OUT_ROW (ROW_ELEMS + NPAIRS) // 3807
#define SROW 132                     // padded row stride (floats), 16B-aligned, bank-friendly
#define TPB 256
#define NTILES 45                    // 9x10/2 tiles of 3x3 over the 27x27 triangle

__device__ __forceinline__ float dot4(float4 a, float4 b) {
    return fmaf(a.x, b.x, fmaf(a.y, b.y, fmaf(a.z, b.z, a.w * b.w)));
}

__global__ __launch_bounds__(TPB)
void fi_kernel(const float* __restrict__ emb, float* __restrict__ out, int B) {
    __shared__ float sE[NF * SROW];   // 27 rows x 132 floats (padded)
    __shared__ float sI[NPAIRS];      // staged interactions for coalesced writeback

    const int b = blockIdx.x;
    if (b >= B) return;
    const int tid = threadIdx.x;

    const float4* __restrict__ in4 = (const float4*)(emb + (size_t)b * ROW_ELEMS);
    float* __restrict__ orow = out + (size_t)b * OUT_ROW;

    // Phase 1: stream input row (float4, 16B-aligned), write-through the flat
    // embedding part of the output (scalar stores: OUT_ROW=3807 is odd so the
    // output row base is only 4B-aligned; stores are still fully coalesced),
    // and stage into padded smem for the dot phase.
    for (int idx = tid; idx < ROW_ELEMS / 4; idx += TPB) {
        float4 v = in4[idx];
        int r = idx >> 5;          // row (32 float4 per row)
        int c = (idx & 31) << 2;   // float offset within row
        *(float4*)&sE[r * SROW + c] = v;
        float* o = orow + (idx << 2);
        o[0] = v.x; o[1] = v.y; o[2] = v.z; o[3] = v.w;
    }
    __syncthreads();

    // Phase 2: 3x3 register-tiled pairwise dots. 45 tiles cover the 27x27
    // upper triangle (incl. diagonal tiles, pruned by i<j). Each k-chunk:
    // 6 LDS.128 feed 36 FFMA -> 4x less smem traffic than per-pair dots.
    if (tid < NTILES) {
        int t = tid, a = 0;
        while (t >= 9 - a) { t -= 9 - a; ++a; }
        const int bb = a + t;          // a <= bb, both in [0,8]
        const int i0 = a * 3, j0 = bb * 3;

        float acc[3][3] = {};
        const float4* Ar0 = (const float4*)&sE[(i0 + 0) * SROW];
        const float4* Ar1 = (const float4*)&sE[(i0 + 1) * SROW];
        const float4* Ar2 = (const float4*)&sE[(i0 + 2) * SROW];
        const float4* Br0 = (const float4*)&sE[(j0 + 0) * SROW];
        const float4* Br1 = (const float4*)&sE[(j0 + 1) * SROW];
        const float4* Br2 = (const float4*)&sE[(j0 + 2) * SROW];

        #pragma unroll 4
        for (int k = 0; k < FD / 4; ++k) {
            float4 a0 = Ar0[k], a1 = Ar1[k], a2 = Ar2[k];
            float4 b0 = Br0[k], b1 = Br1[k], b2 = Br2[k];
            acc[0][0] += dot4(a0, b0);
            acc[0][1] += dot4(a0, b1);
            acc[0][2] += dot4(a0, b2);
            acc[1][0] += dot4(a1, b0);
            acc[1][1] += dot4(a1, b1);
            acc[1][2] += dot4(a1, b2);
            acc[2][0] += dot4(a2, b0);
            acc[2][1] += dot4(a2, b1);
            acc[2][2] += dot4(a2, b2);
        }

        #pragma unroll
        for (int r = 0; r < 3; ++r) {
            #pragma unroll
            for (int c = 0; c < 3; ++c) {
                int i = i0 + r, j = j0 + c;
                if (i < j) {
                    // np.triu_indices(27, k=1) row-major flat index
                    int p = 26 * i - (i * (i - 1)) / 2 + (j - i - 1);
                    sI[p] = acc[r][c];
                }
            }
        }
    }
    __syncthreads();

    // Phase 3: coalesced writeback of the 351 interaction values.
    for (int i = tid; i < NPAIRS; i += TPB) {
        orow[ROW_ELEMS + i] = sI[i];
    }
}

extern "C" void kernel_launch(void* const* d_in, const int* in_sizes, int n_in,
                              void* d_out, int out_size) {
    const float* emb = (const float*)d_in[0];
    float* out = (float*)d_out;
    int B = in_sizes[0] / ROW_ELEMS;   // 16384
    fi_kernel<<<B, TPB>>>(emb, out, B);
}